// round 8
// baseline (speedup 1.0000x reference)
#include <cuda_runtime.h>
#include <stdint.h>
#include <math.h>

#define Bc 8
#define Tc 256
#define Nn 118
#define Fc 3
#define Dc 128
#define Ec 372
#define Gc (Bc*Tc)          // 2048 graphs
#define Mc (Gc*Nn)          // 241664 rows
#define CLN 4               // cluster size for LSTM
#define HST 132             // Hs/Hg row stride (floats)
#define WST 136             // W row stride (floats)

// ---------------- scratch (device globals; no allocation allowed) ----------------
__device__ float g_emb[Gc*Dc];
__device__ float g_xg0[(size_t)Gc*4*Dc]; // precomputed x@Wih0^T + biases (PERMUTED layout)
__device__ float g_final[Bc*Dc];
__device__ int   g_rowoff[Nn+1];
__device__ int   g_csrsrc[Ec];
__device__ float g_csrnorm[Ec];
__device__ float g_invdeg[Nn];

__device__ __forceinline__ float fsig(float x){ return __fdividef(1.0f, 1.0f + __expf(-x)); }
__device__ __forceinline__ float ftanh(float x){ return 2.0f*fsig(2.0f*x) - 1.0f; }
__device__ __forceinline__ float siluf_(float x){ return x*fsig(x); }
__device__ __forceinline__ float tf32f(float x){
    uint32_t u; asm("cvt.rna.tf32.f32 %0, %1;" : "=r"(u) : "f"(x));
    return __uint_as_float(u);
}

__device__ __forceinline__ uint32_t s2u(const void* p){
    uint32_t a;
    asm("{ .reg .u64 t; cvta.to.shared.u64 t, %1; cvt.u32.u64 %0, t; }" : "=r"(a) : "l"(p));
    return a;
}
__device__ __forceinline__ void st_async_f32(uint32_t laddr, uint32_t lmbar, uint32_t peer, float v){
    asm volatile("{ .reg .b32 ra, rb;\n\t"
                 "mapa.shared::cluster.u32 ra, %0, %2;\n\t"
                 "mapa.shared::cluster.u32 rb, %1, %2;\n\t"
                 "st.async.shared::cluster.mbarrier::complete_tx::bytes.b32 [ra], %3, [rb]; }"
                 :: "r"(laddr), "r"(lmbar), "r"(peer), "r"(__float_as_uint(v)) : "memory");
}
__device__ __forceinline__ void mbar_expect_tx(uint32_t mbar, uint32_t bytes){
    asm volatile("mbarrier.arrive.expect_tx.shared.b64 _, [%0], %1;"
                 :: "r"(mbar), "r"(bytes) : "memory");
}
__device__ __forceinline__ void mbar_wait(uint32_t addr, uint32_t parity){
    asm volatile("{\n\t"
        ".reg .pred P;\n\t"
        "WL%=:\n\t"
        "mbarrier.try_wait.parity.acquire.cluster.shared::cta.b64 P, [%0], %1, 0x989680;\n\t"
        "@!P bra WL%=;\n\t"
        "}" :: "r"(addr), "r"(parity) : "memory");
}

// ---------------- prep: decode edge_index (int32 or int64), build CSR ----------------
__global__ void k_prep(const int* __restrict__ ei) {
    if (threadIdx.x != 0) return;
    int ssrc[Ec], sdst[Ec];
    bool is64 = true;
    for (int i = 1; i < 2*Ec; i += 2) { if (ei[i] != 0) { is64 = false; break; } }
    for (int e = 0; e < Ec; e++) {
        if (is64) { ssrc[e] = ei[2*e]; sdst[e] = ei[2*(Ec+e)]; }
        else      { ssrc[e] = ei[e];   sdst[e] = ei[Ec+e];     }
    }
    float deg[Nn];
    for (int n = 0; n < Nn; n++) deg[n] = 1.0f;
    for (int e = 0; e < Ec; e++) deg[sdst[e]] += 1.0f;
    float inv[Nn];
    for (int n = 0; n < Nn; n++) {
        g_invdeg[n] = 1.0f/deg[n];
        inv[n] = 1.0f/sqrtf(deg[n]);
    }
    int cnt[Nn];
    for (int n = 0; n < Nn; n++) cnt[n] = 0;
    for (int e = 0; e < Ec; e++) cnt[sdst[e]]++;
    int off = 0;
    for (int n = 0; n < Nn; n++) { g_rowoff[n] = off; off += cnt[n]; cnt[n] = g_rowoff[n]; }
    g_rowoff[Nn] = off;
    for (int e = 0; e < Ec; e++) {
        int d = sdst[e]; int p = cnt[d]++;
        g_csrsrc[p]  = ssrc[e];
        g_csrnorm[p] = inv[ssrc[e]] * inv[d];
    }
}

// ---------------- mega: whole GCN stack per graph in one block ----------------
__global__ void __launch_bounds__(512,1) k_mega(const float* __restrict__ snap,
        const float* __restrict__ scale, const float* __restrict__ shift,
        const float* __restrict__ W1, const float* __restrict__ b1,
        const float* __restrict__ W2, const float* __restrict__ b2,
        const float* __restrict__ W3, const float* __restrict__ b3) {
    extern __shared__ float dyn[];
    float* Hg = dyn;
    float* Hs = Hg + 128*HST;
    float* Ws = Hs + 128*HST;
    __shared__ int   soff[Nn+1];
    __shared__ int   ssrc[Ec];
    __shared__ float snorm[Ec];
    __shared__ float sinvd[Nn];
    __shared__ float xs[Nn*Fc];
    __shared__ float sW1[Fc*Dc];
    __shared__ float sred[512];

    int t = threadIdx.x;
    int g = blockIdx.x;
    int c = t & 127, qr = t >> 7;

    for (int i = t; i < Nn*Fc; i += 512) {
        int f = i - (i/3)*3;
        xs[i] = snap[(size_t)g*Nn*Fc + i]*scale[f] + shift[f];
    }
    for (int i = t; i < Fc*Dc; i += 512) sW1[i] = W1[i];
    for (int i = t; i <= Nn; i += 512) soff[i] = g_rowoff[i];
    for (int i = t; i < Ec; i += 512) { ssrc[i] = g_csrsrc[i]; snorm[i] = g_csrnorm[i]; }
    if (t < Nn) sinvd[t] = g_invdeg[t];
    for (int i = t; i < 128*128; i += 512) {
        int k = i >> 7, n = i & 127;
        Ws[k*WST + n] = tf32f(W2[i]);
    }
    for (int i = t; i < 10*128; i += 512) {
        int r = i >> 7, cc = i & 127;
        Hs[(Nn + r)*HST + cc] = 0.f;
    }
    __syncthreads();

    for (int i = t; i < Nn*128; i += 512) {
        int n = i >> 7, cc = i & 127;
        Hg[n*HST + cc] = fmaf(xs[n*3], sW1[cc],
                         fmaf(xs[n*3+1], sW1[128+cc], xs[n*3+2]*sW1[256+cc]));
    }
    __syncthreads();

    {
        float b = b1[c];
        for (int n = qr; n < Nn; n += 4) {
            float a = Hg[n*HST + c] * sinvd[n];
            int e0 = soff[n], e1 = soff[n+1];
            for (int e = e0; e < e1; e++) a += Hg[ssrc[e]*HST + c] * snorm[e];
            Hs[n*HST + c] = tf32f(siluf_(a + b));
        }
    }
    __syncthreads();

    int wid = t >> 5, lane = t & 31;
    int mbase = (wid & 7) * 16, nhalf = (wid >> 3) * 64;
    int gq = lane >> 2, tig = lane & 3;

    #define DO_GEMM() do { \
        float acc[8][4]; \
        _Pragma("unroll") \
        for (int j = 0; j < 8; j++) { acc[j][0]=0.f; acc[j][1]=0.f; acc[j][2]=0.f; acc[j][3]=0.f; } \
        const float* Ar0 = Hs + (mbase+gq)*HST; \
        const float* Ar1 = Hs + (mbase+gq+8)*HST; \
        for (int k0 = 0; k0 < 128; k0 += 8) { \
            uint32_t a0 = __float_as_uint(Ar0[k0+tig]); \
            uint32_t a1 = __float_as_uint(Ar1[k0+tig]); \
            uint32_t a2 = __float_as_uint(Ar0[k0+tig+4]); \
            uint32_t a3 = __float_as_uint(Ar1[k0+tig+4]); \
            const float* B0 = Ws + (k0+tig)*WST + nhalf + gq; \
            const float* B1 = Ws + (k0+tig+4)*WST + nhalf + gq; \
            _Pragma("unroll") \
            for (int j = 0; j < 8; j++) { \
                uint32_t b0 = __float_as_uint(B0[8*j]); \
                uint32_t b1_ = __float_as_uint(B1[8*j]); \
                asm volatile("mma.sync.aligned.m16n8k8.row.col.f32.tf32.tf32.f32 " \
                    "{%0,%1,%2,%3}, {%4,%5,%6,%7}, {%8,%9}, {%0,%1,%2,%3};" \
                    : "+f"(acc[j][0]), "+f"(acc[j][1]), "+f"(acc[j][2]), "+f"(acc[j][3]) \
                    : "r"(a0), "r"(a1), "r"(a2), "r"(a3), "r"(b0), "r"(b1_)); \
            } \
        } \
        _Pragma("unroll") \
        for (int j = 0; j < 8; j++) { \
            float* o0 = Hg + (mbase+gq)*HST   + nhalf + 8*j + 2*tig; \
            float* o1 = Hg + (mbase+gq+8)*HST + nhalf + 8*j + 2*tig; \
            o0[0] = acc[j][0]; o0[1] = acc[j][1]; \
            o1[0] = acc[j][2]; o1[1] = acc[j][3]; \
        } \
    } while(0)

    DO_GEMM();           // GEMM2
    __syncthreads();

    {
        float b = b2[c];
        for (int n = qr; n < Nn; n += 4) {
            float a = Hg[n*HST + c] * sinvd[n];
            int e0 = soff[n], e1 = soff[n+1];
            for (int e = e0; e < e1; e++) a += Hg[ssrc[e]*HST + c] * snorm[e];
            Hs[n*HST + c] = tf32f(siluf_(a + b));
        }
        for (int i = t; i < 128*128; i += 512) {
            int k = i >> 7, n = i & 127;
            Ws[k*WST + n] = tf32f(W3[i]);
        }
    }
    __syncthreads();

    DO_GEMM();           // GEMM3
    __syncthreads();

    {
        float b = b3[c];
        float macc = 0.f;
        for (int n = qr; n < Nn; n += 4) {
            float a = Hg[n*HST + c] * sinvd[n];
            int e0 = soff[n], e1 = soff[n+1];
            for (int e = e0; e < e1; e++) a += Hg[ssrc[e]*HST + c] * snorm[e];
            macc += siluf_(a + b);
        }
        sred[t] = macc;
        __syncthreads();
        if (t < 128)
            g_emb[g*Dc + t] = (sred[t] + sred[128+t] + sred[256+t] + sred[384+t]) * (1.0f/(float)Nn);
    }
    #undef DO_GEMM
}

// ---------------- xg0 = emb @ Wih0^T + bih0 + bhh0 (PERMUTED for k_lstm5 lanes) ----------
// gate row j = q*128 + e. cta=e>>5, ec=e&31, w=ec>>3, ei=ec&7, lane=ei*4+q.
// pidx = cta*128 + w*32 + lane
__global__ void __launch_bounds__(512) k_xg0(const float* __restrict__ Wih0,
        const float* __restrict__ bih0, const float* __restrict__ bhh0) {
    __shared__ float es[16*128];
    int j = threadIdx.x;
    int m0 = blockIdx.x * 16;
    for (int i = j; i < 2048; i += 512) es[i] = g_emb[m0*128 + i];
    __syncthreads();
    const float4* wr = (const float4*)(Wih0 + (size_t)j*128);
    float acc[16];
    #pragma unroll
    for (int r = 0; r < 16; r++) acc[r] = 0.f;
    #pragma unroll 4
    for (int k4 = 0; k4 < 32; k4++) {
        float4 w = wr[k4];
        #pragma unroll
        for (int r = 0; r < 16; r++) {
            float4 e = *(const float4*)&es[r*128 + k4*4];
            acc[r] += w.x*e.x + w.y*e.y + w.z*e.z + w.w*e.w;
        }
    }
    float bb = bih0[j] + bhh0[j];
    int q = j >> 7, e = j & 127;
    int cta = e >> 5, ec = e & 31;
    int w = ec >> 3, ei = ec & 7;
    int pidx = cta*128 + w*32 + ei*4 + q;
    #pragma unroll
    for (int r = 0; r < 16; r++)
        g_xg0[(size_t)(m0+r)*512 + pidx] = acc[r] + bb;
}

// ---------------- LSTM v5: warp-autonomous gates, shfl activation, 1 bar/step --------
// 4-CTA cluster per batch, 384 threads (12 warps) per CTA.
// Warps 0-3: layer0. lane = ei*4 + g (ei 0..7). row = g*128 + cta*32 + w*8 + ei.
// Warps 4-11: layer1. lane = ei*8 + g*2 + half (ei 0..3). row = g*128 + cta*32 + v*4 + ei.
//   half=0: Wih1 row dot h0[s-1]; half=1: Whh1 row dot h1[s-2]; pair-summed via shfl.
// Iteration s computes layer0 step s and layer1 step s-1; one exchange + one bar.
__global__ void __launch_bounds__(384,1) __cluster_dims__(CLN,1,1)
k_lstm5(const float* __restrict__ Whh0, const float* __restrict__ Wih1,
        const float* __restrict__ Whh1,
        const float* __restrict__ bih1, const float* __restrict__ bhh1) {
    __shared__ float h0buf[2][128];
    __shared__ float h1buf[2][128];
    __shared__ __align__(8) unsigned long long mbs[2];

    int t    = threadIdx.x;
    int w    = t >> 5;
    int l    = t & 31;
    int cta  = blockIdx.x & (CLN-1);
    int b    = blockIdx.x / CLN;
    bool isL0 = (w < 4);

    int row; const float* Wsel; float bias1 = 0.f;
    if (isL0) {
        int ei = l >> 2, g = l & 3;
        row = g*128 + cta*32 + w*8 + ei;
        Wsel = Whh0;
    } else {
        int v = w - 4;
        int ei = l >> 3, g = (l >> 1) & 3, half = l & 1;
        row = g*128 + cta*32 + v*4 + ei;
        Wsel = half ? Whh1 : Wih1;
        if (!half) bias1 = bih1[row] + bhh1[row];
    }
    float4 wreg[32];
    {
        const float4* gsrc = (const float4*)(Wsel + (size_t)row*128);
        #pragma unroll
        for (int k = 0; k < 32; k++) wreg[k] = gsrc[k];
    }

    if (t < 128) { h0buf[0][t] = 0.f; h0buf[1][t] = 0.f; h1buf[0][t] = 0.f; h1buf[1][t] = 0.f; }
    uint32_t mba0 = s2u(&mbs[0]), mba1 = s2u(&mbs[1]);
    uint32_t h0a = s2u(h0buf), h1a = s2u(h1buf);
    if (t == 0) {
        asm volatile("mbarrier.init.shared.b64 [%0], %1;" :: "r"(mba0), "r"(1) : "memory");
        asm volatile("mbarrier.init.shared.b64 [%0], %1;" :: "r"(mba1), "r"(1) : "memory");
    }
    __syncthreads();
    asm volatile("barrier.cluster.arrive.aligned;" ::: "memory");
    asm volatile("barrier.cluster.wait.aligned;"   ::: "memory");

    float c0 = 0.f, c1 = 0.f;
    const float* xg = g_xg0 + (size_t)b*256*512 + cta*128 + (w*32 + l);  // valid for isL0

    for (int s = 0; s < 257; s++) {
        int p = s & 1;
        bool last = (s == 256);
        uint32_t mba = (s & 1) ? mba1 : mba0;
        uint32_t parity = (uint32_t)((s >> 1) & 1);
        if (t == 0 && !last) mbar_expect_tx(mba, 1024u);
        float xv = (isL0 && !last) ? xg[(size_t)s*512] : 0.f;

        // ---- dot product (h loads are warp-broadcast LDS) ----
        float d;
        {
            const float4* hv = isL0 ? (const float4*)h0buf[p]
                             : ((l & 1) ? (const float4*)h1buf[p] : (const float4*)h0buf[p]);
            float4 a = make_float4(0,0,0,0), a2 = make_float4(0,0,0,0);
            #pragma unroll
            for (int k = 0; k < 32; k += 2) {
                float4 wv = wreg[k],   h = hv[k];
                a.x += wv.x*h.x; a.y += wv.y*h.y; a.z += wv.z*h.z; a.w += wv.w*h.w;
                float4 w2 = wreg[k+1], h2 = hv[k+1];
                a2.x += w2.x*h2.x; a2.y += w2.y*h2.y; a2.z += w2.z*h2.z; a2.w += w2.w*h2.w;
            }
            d = ((a.x+a.y)+(a.z+a.w)) + ((a2.x+a2.y)+(a2.z+a2.w));
        }
        // all reads of parity-p buffers must complete CTA-wide before any store
        __syncthreads();

        if (isL0) {
            if (!last) {
                d += xv;
                int base = l & ~3;
                float di  = __shfl_sync(0xFFFFFFFFu, d, base+0);
                float df  = __shfl_sync(0xFFFFFFFFu, d, base+1);
                float dg  = __shfl_sync(0xFFFFFFFFu, d, base+2);
                float do_ = __shfl_sync(0xFFFFFFFFu, d, base+3);
                if ((l & 3) == 0) {
                    c0 = fsig(df)*c0 + fsig(di)*ftanh(dg);
                    float hv0 = fsig(do_)*ftanh(c0);
                    int elem = cta*32 + w*8 + (l >> 2);
                    uint32_t dst = h0a + (uint32_t)(((p^1)*128 + elem)*4);
                    #pragma unroll
                    for (int peer = 0; peer < CLN; peer++)
                        st_async_f32(dst, mba, (uint32_t)peer, hv0);
                }
            }
        } else {
            d += bias1;                                // only half==0 lanes carry bias
            d += __shfl_xor_sync(0xFFFFFFFFu, d, 1);   // Wih1·h0 + Whh1·h1
            int base = l & ~7;
            float di  = __shfl_sync(0xFFFFFFFFu, d, base+0);
            float df  = __shfl_sync(0xFFFFFFFFu, d, base+2);
            float dg  = __shfl_sync(0xFFFFFFFFu, d, base+4);
            float do_ = __shfl_sync(0xFFFFFFFFu, d, base+6);
            if ((l & 7) == 0) {
                float hv1;
                if (s == 0) {
                    hv1 = 0.f;
                } else {
                    c1 = fsig(df)*c1 + fsig(di)*ftanh(dg);
                    hv1 = fsig(do_)*ftanh(c1);
                }
                int elem = cta*32 + (w-4)*4 + (l >> 3);
                if (!last) {
                    uint32_t dst = h1a + (uint32_t)(((p^1)*128 + elem)*4);
                    #pragma unroll
                    for (int peer = 0; peer < CLN; peer++)
                        st_async_f32(dst, mba, (uint32_t)peer, hv1);
                } else {
                    g_final[b*128 + elem] = hv1;       // h1[255]
                }
            }
        }
        if (!last) mbar_wait(mba, parity);
    }
}

// ---------------- head MLP ----------------
__global__ void __launch_bounds__(128) k_head(const float* __restrict__ hW1, const float* __restrict__ hb1,
        const float* __restrict__ hW2, const float* __restrict__ hb2,
        const float* __restrict__ hW3, const float* __restrict__ hb3,
        float* __restrict__ out) {
    __shared__ float sf[8*128], s1[8*128], s2[8*64];
    int t = threadIdx.x;
    for (int i = t; i < 1024; i += 128) sf[i] = g_final[i];
    __syncthreads();
    {
        int d = t;
        for (int b = 0; b < 8; b++) {
            float acc = hb1[d];
            for (int k = 0; k < 128; k++) acc += sf[b*128+k]*hW1[k*128+d];
            s1[b*128+d] = siluf_(acc);
        }
    }
    __syncthreads();
    if (t < 64) {
        int e = t;
        for (int b = 0; b < 8; b++) {
            float acc = hb2[e];
            for (int k = 0; k < 128; k++) acc += s1[b*128+k]*hW2[k*64+e];
            s2[b*64+e] = siluf_(acc);
        }
    }
    __syncthreads();
    if (t < 16) {
        int b = t >> 1, o = t & 1;
        float acc = hb3[o];
        for (int k = 0; k < 64; k++) acc += s2[b*64+k]*hW3[k*2+o];
        float sp = fmaxf(acc, 0.f) + log1pf(expf(-fabsf(acc)));
        out[b*2+o] = sp + 1e-6f;
    }
}

// ---------------- launch ----------------
extern "C" void kernel_launch(void* const* d_in, const int* in_sizes, int n_in,
                              void* d_out, int out_size) {
    const float* snap  = (const float*)d_in[0];
    const int*   ei    = (const int*)  d_in[1];
    const float* scale = (const float*)d_in[2];
    const float* shift = (const float*)d_in[3];
    const float* W1    = (const float*)d_in[4];
    const float* b1    = (const float*)d_in[5];
    const float* W2    = (const float*)d_in[6];
    const float* b2    = (const float*)d_in[7];
    const float* W3    = (const float*)d_in[8];
    const float* b3    = (const float*)d_in[9];
    const float* Wih0  = (const float*)d_in[10];
    const float* Whh0  = (const float*)d_in[11];
    const float* bih0  = (const float*)d_in[12];
    const float* bhh0  = (const float*)d_in[13];
    const float* Wih1  = (const float*)d_in[14];
    const float* Whh1  = (const float*)d_in[15];
    const float* bih1  = (const float*)d_in[16];
    const float* bhh1  = (const float*)d_in[17];
    const float* hW1   = (const float*)d_in[18];
    const float* hb1   = (const float*)d_in[19];
    const float* hW2   = (const float*)d_in[20];
    const float* hb2   = (const float*)d_in[21];
    const float* hW3   = (const float*)d_in[22];
    const float* hb3   = (const float*)d_in[23];
    float* out = (float*)d_out;

    const int megaSmem = (128*HST + 128*HST + 128*WST)*(int)sizeof(float); // 204800
    cudaFuncSetAttribute(k_mega, cudaFuncAttributeMaxDynamicSharedMemorySize, megaSmem);

    k_prep<<<1, 32>>>(ei);
    k_mega<<<Gc, 512, megaSmem>>>(snap, scale, shift, W1, b1, W2, b2, W3, b3);
    k_xg0<<<Gc/16, 512>>>(Wih0, bih0, bhh0);
    k_lstm5<<<Bc*CLN, 384>>>(Whh0, Wih1, Whh1, bih1, bhh1);
    k_head<<<1, 128>>>(hW1, hb1, hW2, hb2, hW3, hb3, out);
}